// round 6
// baseline (speedup 1.0000x reference)
#include <cuda_runtime.h>
#include <math.h>

#define BATCH 2
#define NP    4096
#define HH    128
#define WW    128
#define KK    8
#define RAD   0.05f
#define RAD2  (RAD * RAD)
#define TILE  8
#define TX    (WW / TILE)    // 16
#define TYN   (HH / TILE)    // 16
#define NTILES (TX * TYN)    // 256
#define LPP   4              // lanes per pixel
#define NPIX  (TILE * TILE)  // 64
#define THREADS (NPIX * LPP) // 256
#define CHUNK 512

#define ZINF 3.0e38f

// Global scratch (no cudaMalloc allowed)
__device__ int    g_cnt[BATCH * NTILES];          // zero-init at load; raster re-zeroes
__device__ float4 g_list[BATCH * NTILES * NP];    // un-overflowable capacity

// ---------------------------------------------------------------------------
// Kernel A: world->view->NDC transform + scatter float4 record into tiles
// ---------------------------------------------------------------------------
__global__ void transform_bin_kernel(const float* __restrict__ pts,
                                     const float* __restrict__ Rm,
                                     const float* __restrict__ Tv,
                                     const float* __restrict__ Fc) {
    int t = blockIdx.x * blockDim.x + threadIdx.x;
    if (t >= BATCH * NP) return;
    int b = t / NP;
    int p = t - b * NP;

    float p0 = pts[t * 3 + 0];
    float p1 = pts[t * 3 + 1];
    float p2 = pts[t * 3 + 2];
    const float* Rb = Rm + b * 9;
    const float* Tb = Tv + b * 3;

    // row-vector convention: v[j] = sum_i p[i] * R[i][j] + T[j]
    float xv = p0 * Rb[0] + p1 * Rb[3] + p2 * Rb[6] + Tb[0];
    float yv = p0 * Rb[1] + p1 * Rb[4] + p2 * Rb[7] + Tb[1];
    float zv = p0 * Rb[2] + p1 * Rb[5] + p2 * Rb[8] + Tb[2];

    float f = Fc[b];
    float x = f * xv / zv;   // IEEE div, matches reference
    float y = f * yv / zv;

    if (!(zv > 0.0f)) return;

    // pixel ix covered iff |gx(ix) - x| < r, gx(ix) = 1 - (ix+0.5)/64
    float lox = 64.0f * (1.0f - x - RAD) - 0.5f;
    float hix = 64.0f * (1.0f - x + RAD) - 0.5f;
    float loy = 64.0f * (1.0f - y - RAD) - 0.5f;
    float hiy = 64.0f * (1.0f - y + RAD) - 0.5f;

    if (!(hix >= 0.0f) || !(lox <= (float)(WW - 1))) return;
    if (!(hiy >= 0.0f) || !(loy <= (float)(HH - 1))) return;

    int ix0 = max(0, (int)floorf(fmaxf(lox, 0.0f)));
    int ix1 = min(WW - 1, (int)ceilf(fminf(hix, (float)(WW - 1))));
    int iy0 = max(0, (int)floorf(fmaxf(loy, 0.0f)));
    int iy1 = min(HH - 1, (int)ceilf(fminf(hiy, (float)(HH - 1))));
    if (ix0 > ix1 || iy0 > iy1) return;

    int tx0 = ix0 / TILE, tx1 = ix1 / TILE;
    int ty0 = iy0 / TILE, ty1 = iy1 / TILE;

    float4 rec = make_float4(x, y, zv, (float)p);
    for (int ty = ty0; ty <= ty1; ty++) {
        for (int tx = tx0; tx <= tx1; tx++) {
            int tile = b * NTILES + ty * TX + tx;
            int pos = atomicAdd(&g_cnt[tile], 1);
            g_list[tile * NP + pos] = rec;
        }
    }
}

// ---------------------------------------------------------------------------
// Kernel B: per-tile raster. 8x8 tile, 4 lanes/pixel (256 thr, 8 warps).
// Each lane scans a 4-stride slice; in-warp shuffle merge of sorted top-8s.
// ---------------------------------------------------------------------------
__global__ void __launch_bounds__(THREADS) raster_kernel(float* __restrict__ out) {
    __shared__ float4 sc[CHUNK];   // 8 KB
    __shared__ int s_n;

    const int tx = blockIdx.x, ty = blockIdx.y, b = blockIdx.z;
    const int tid = threadIdx.x;
    const int tile = b * NTILES + ty * TX + tx;

    if (tid == 0) {
        s_n = g_cnt[tile];
        g_cnt[tile] = 0;           // reset for next graph replay (own counter only)
    }
    __syncthreads();
    const int n = s_n;
    const float4* __restrict__ list = g_list + tile * NP;

    const int grp = tid >> 2;          // pixel group 0..63
    const int sub = tid & 3;           // lane within pixel
    const int lx = grp & (TILE - 1), ly = grp / TILE;
    const int px = tx * TILE + lx;
    const int py = ty * TILE + ly;
    const float gx = 1.0f - (px + 0.5f) * (1.0f / 64.0f);
    const float gy = 1.0f - (py + 0.5f) * (1.0f / 64.0f);

    float zb[KK], db[KK], ib[KK];
#pragma unroll
    for (int k = 0; k < KK; k++) { zb[k] = ZINF; db[k] = -1.0f; ib[k] = -1.0f; }

    // ---- strided scan: lane `sub` handles candidates j ≡ sub (mod 4) ----
    for (int base = 0; base < n; base += CHUNK) {
        int m = min(CHUNK, n - base);
        __syncthreads();
        for (int i = tid; i < m; i += THREADS)
            sc[i] = list[base + i];            // coalesced 16B loads
        __syncthreads();

        for (int j = sub; j < m; j += LPP) {
            float4 c = sc[j];                  // 4 distinct addrs/warp: conflict-free
            float dx = gx - c.x;
            float dy = gy - c.y;
            float d2 = fmaf(dx, dx, dy * dy);
            if (d2 < RAD2 && c.z < zb[KK - 1]) {
                float zi = c.z, di = d2, ii = c.w;
#pragma unroll
                for (int k = 0; k < KK; k++) {
                    if (zi < zb[k]) {
                        float t;
                        t = zb[k]; zb[k] = zi; zi = t;
                        t = db[k]; db[k] = di; di = t;
                        t = ib[k]; ib[k] = ii; ii = t;
                    }
                }
            }
        }
    }

    // ---- in-warp merge of the 4 partial sorted lists (xor 1, then xor 2) ----
#pragma unroll
    for (int d = 1; d <= 2; d <<= 1) {
        float tz[KK], td[KK], ti[KK];
#pragma unroll
        for (int k = 0; k < KK; k++) { tz[k] = zb[k]; td[k] = db[k]; ti[k] = ib[k]; }
#pragma unroll
        for (int k = 0; k < KK; k++) {
            float zi = __shfl_xor_sync(0xffffffffu, tz[k], d);
            float di = __shfl_xor_sync(0xffffffffu, td[k], d);
            float ii = __shfl_xor_sync(0xffffffffu, ti[k], d);
            if (!(zi < zb[KK - 1])) continue;  // incoming sorted: rest also fail,
                                               // but keep flat (no break divergence)
#pragma unroll
            for (int q = 0; q < KK; q++) {
                if (zi < zb[q]) {
                    float t;
                    t = zb[q]; zb[q] = zi; zi = t;
                    t = db[q]; db[q] = di; di = t;
                    t = ib[q]; ib[q] = ii; ii = t;
                }
            }
        }
    }

    // ---- Output: all 4 lanes hold identical lists; split k across lanes ----
    const int N = BATCH * HH * WW * KK;
    const int obase = ((b * HH + py) * WW + px) * KK;
#pragma unroll
    for (int k2 = 0; k2 < KK / LPP; k2++) {
        int k = sub * (KK / LPP) + k2;
        bool v = zb[k] < ZINF;
        out[obase + k]         = v ? ib[k] : -1.0f;
        out[N + obase + k]     = v ? zb[k] : -1.0f;
        out[2 * N + obase + k] = v ? db[k] : -1.0f;
    }
}

// ---------------------------------------------------------------------------
extern "C" void kernel_launch(void* const* d_in, const int* in_sizes, int n_in,
                              void* d_out, int out_size) {
    const float* pts = (const float*)d_in[0];
    const float* Rm  = (const float*)d_in[1];
    const float* Tv  = (const float*)d_in[2];
    const float* Fc  = (const float*)d_in[3];
    float* out = (float*)d_out;

    transform_bin_kernel<<<(BATCH * NP + 255) / 256, 256>>>(pts, Rm, Tv, Fc);
    raster_kernel<<<dim3(TX, TYN, BATCH), THREADS>>>(out);
}

// round 7
// speedup vs baseline: 1.0640x; 1.0640x over previous
#include <cuda_runtime.h>
#include <math.h>

#define BATCH 2
#define NP    4096
#define HH    128
#define WW    128
#define KK    8
#define RAD   0.05f
#define RAD2  (RAD * RAD)
#define TILE  8
#define TX    (WW / TILE)    // 16
#define TYN   (HH / TILE)    // 16
#define NTILES (TX * TYN)    // 256
#define NPIX  (TILE * TILE)  // 64 threads per CTA
#define CHUNK 512

#define ZINF 3.0e38f

// Global scratch (no cudaMalloc allowed)
__device__ int    g_cnt[BATCH * NTILES];          // zero-init at load; raster re-zeroes
__device__ float4 g_list[BATCH * NTILES * NP];    // un-overflowable capacity

// ---------------------------------------------------------------------------
// Kernel A: world->view->NDC transform + scatter float4 record into tiles
// ---------------------------------------------------------------------------
__global__ void transform_bin_kernel(const float* __restrict__ pts,
                                     const float* __restrict__ Rm,
                                     const float* __restrict__ Tv,
                                     const float* __restrict__ Fc) {
    int t = blockIdx.x * blockDim.x + threadIdx.x;
    if (t >= BATCH * NP) return;
    int b = t / NP;
    int p = t - b * NP;

    float p0 = pts[t * 3 + 0];
    float p1 = pts[t * 3 + 1];
    float p2 = pts[t * 3 + 2];
    const float* Rb = Rm + b * 9;
    const float* Tb = Tv + b * 3;

    // row-vector convention: v[j] = sum_i p[i] * R[i][j] + T[j]
    float xv = p0 * Rb[0] + p1 * Rb[3] + p2 * Rb[6] + Tb[0];
    float yv = p0 * Rb[1] + p1 * Rb[4] + p2 * Rb[7] + Tb[1];
    float zv = p0 * Rb[2] + p1 * Rb[5] + p2 * Rb[8] + Tb[2];

    float f = Fc[b];
    float x = f * xv / zv;   // IEEE div, matches reference
    float y = f * yv / zv;

    if (!(zv > 0.0f)) return;

    // pixel ix covered iff |gx(ix) - x| < r, gx(ix) = 1 - (ix+0.5)/64
    float lox = 64.0f * (1.0f - x - RAD) - 0.5f;
    float hix = 64.0f * (1.0f - x + RAD) - 0.5f;
    float loy = 64.0f * (1.0f - y - RAD) - 0.5f;
    float hiy = 64.0f * (1.0f - y + RAD) - 0.5f;

    if (!(hix >= 0.0f) || !(lox <= (float)(WW - 1))) return;
    if (!(hiy >= 0.0f) || !(loy <= (float)(HH - 1))) return;

    int ix0 = max(0, (int)floorf(fmaxf(lox, 0.0f)));
    int ix1 = min(WW - 1, (int)ceilf(fminf(hix, (float)(WW - 1))));
    int iy0 = max(0, (int)floorf(fmaxf(loy, 0.0f)));
    int iy1 = min(HH - 1, (int)ceilf(fminf(hiy, (float)(HH - 1))));
    if (ix0 > ix1 || iy0 > iy1) return;

    int tx0 = ix0 / TILE, tx1 = ix1 / TILE;
    int ty0 = iy0 / TILE, ty1 = iy1 / TILE;

    float4 rec = make_float4(x, y, zv, (float)p);
    for (int ty = ty0; ty <= ty1; ty++) {
        for (int tx = tx0; tx <= tx1; tx++) {
            int tile = b * NTILES + ty * TX + tx;
            int pos = atomicAdd(&g_cnt[tile], 1);
            g_list[tile * NP + pos] = rec;
        }
    }
}

// ---------------------------------------------------------------------------
// Kernel B: per-tile raster. 8x8 tile, 64 threads = 1/pixel.
// Pass 1: branch-free FMNMX ladder keeps 8 smallest z.
// Pass 2: sparse equality match fills d2/idx for the 8 winners.
// ---------------------------------------------------------------------------
__global__ void __launch_bounds__(NPIX) raster_kernel(float* __restrict__ out) {
    __shared__ float4 sc[CHUNK];   // 8 KB
    __shared__ int s_n;

    const int tx = blockIdx.x, ty = blockIdx.y, b = blockIdx.z;
    const int tid = threadIdx.x;
    const int tile = b * NTILES + ty * TX + tx;

    if (tid == 0) {
        s_n = g_cnt[tile];
        g_cnt[tile] = 0;           // reset for next graph replay (own counter only)
    }
    __syncthreads();
    const int n = s_n;
    const float4* __restrict__ list = g_list + tile * NP;

    const int lx = tid & (TILE - 1), ly = tid / TILE;
    const int px = tx * TILE + lx;
    const int py = ty * TILE + ly;
    const float gx = 1.0f - (px + 0.5f) * (1.0f / 64.0f);
    const float gy = 1.0f - (py + 0.5f) * (1.0f / 64.0f);

    float zb[KK], db[KK], ib[KK];
#pragma unroll
    for (int k = 0; k < KK; k++) { zb[k] = ZINF; db[k] = -1.0f; ib[k] = -1.0f; }

    if (n <= CHUNK) {
        // ------------------- fast path: whole list resident in smem --------
        for (int i = tid; i < n; i += NPIX)
            sc[i] = list[i];                  // coalesced 16B loads
        __syncthreads();

        // Pass 1: branch-free sorted top-8 of z (misses keyed +INF)
#pragma unroll 2
        for (int j = 0; j < n; j++) {
            float4 c = sc[j];                 // LDS.128 broadcast
            float dx = gx - c.x;
            float dy = gy - c.y;
            float d2 = fmaf(dx, dx, dy * dy);
            float key = (d2 < RAD2) ? c.z : ZINF;
#pragma unroll
            for (int k = 0; k < KK; k++) {
                float lo = fminf(zb[k], key);
                key = fmaxf(zb[k], key);
                zb[k] = lo;
            }
        }
        const float z7 = zb[KK - 1];

        // Pass 2: sparse exact-equality fill of d2/idx (z distinct)
#pragma unroll 2
        for (int j = 0; j < n; j++) {
            float4 c = sc[j];
            float dx = gx - c.x;
            float dy = gy - c.y;
            float d2 = fmaf(dx, dx, dy * dy);
            if (d2 < RAD2 && c.z <= z7) {
#pragma unroll
                for (int k = 0; k < KK; k++) {
                    if (c.z == zb[k]) { db[k] = d2; ib[k] = c.w; }
                }
            }
        }
    } else {
        // ---------- safety fallback (never taken with this data) -----------
        for (int base = 0; base < n; base += CHUNK) {
            int m = min(CHUNK, n - base);
            __syncthreads();
            for (int i = tid; i < m; i += NPIX) sc[i] = list[base + i];
            __syncthreads();
            for (int j = 0; j < m; j++) {
                float4 c = sc[j];
                float dx = gx - c.x;
                float dy = gy - c.y;
                float d2 = fmaf(dx, dx, dy * dy);
                if (d2 < RAD2 && c.z < zb[KK - 1]) {
                    float zi = c.z, di = d2, ii = c.w;
#pragma unroll
                    for (int k = 0; k < KK; k++) {
                        if (zi < zb[k]) {
                            float t;
                            t = zb[k]; zb[k] = zi; zi = t;
                            t = db[k]; db[k] = di; di = t;
                            t = ib[k]; ib[k] = ii; ii = t;
                        }
                    }
                }
            }
        }
    }

    // ---- Output: [idx | zbuf | dists], each [B,H,W,K] ----
    const int N = BATCH * HH * WW * KK;
    const int obase = ((b * HH + py) * WW + px) * KK;
#pragma unroll
    for (int k = 0; k < KK; k++) {
        bool v = zb[k] < ZINF;
        out[obase + k]         = v ? ib[k] : -1.0f;
        out[N + obase + k]     = v ? zb[k] : -1.0f;
        out[2 * N + obase + k] = v ? db[k] : -1.0f;
    }
}

// ---------------------------------------------------------------------------
extern "C" void kernel_launch(void* const* d_in, const int* in_sizes, int n_in,
                              void* d_out, int out_size) {
    const float* pts = (const float*)d_in[0];
    const float* Rm  = (const float*)d_in[1];
    const float* Tv  = (const float*)d_in[2];
    const float* Fc  = (const float*)d_in[3];
    float* out = (float*)d_out;

    transform_bin_kernel<<<(BATCH * NP + 255) / 256, 256>>>(pts, Rm, Tv, Fc);
    raster_kernel<<<dim3(TX, TYN, BATCH), NPIX>>>(out);
}

// round 8
// speedup vs baseline: 1.1480x; 1.0789x over previous
#include <cuda_runtime.h>
#include <math.h>

#define BATCH 2
#define NP    4096
#define HH    128
#define WW    128
#define KK    8
#define RAD   0.05f
#define RAD2  (RAD * RAD)
#define TILE  8
#define TX    (WW / TILE)    // 16
#define TYN   (HH / TILE)    // 16
#define NTILES (TX * TYN)    // 256
#define NCTA  (TX * TYN * BATCH)  // 512
#define THREADS 128          // 64 pixels * 2 lanes
#define CHUNK 512

#define ZINF 3.0e38f

// Global scratch (no cudaMalloc allowed)
__device__ int      g_cnt[BATCH * NTILES];       // zero-init; reset in-kernel each run
__device__ float4   g_list[BATCH * NTILES * NP];
__device__ unsigned g_arrive = 0;                // barrier arrivals (reset each barrier)
__device__ unsigned g_epoch  = 0;                // monotonic across graph replays

__global__ void __launch_bounds__(THREADS) raster_fused(
        const float* __restrict__ pts,
        const float* __restrict__ Rm,
        const float* __restrict__ Tv,
        const float* __restrict__ Fc,
        float* __restrict__ out) {
    __shared__ float4 sc[CHUNK];   // 8 KB
    __shared__ int s_n;

    const int bx = blockIdx.x, by = blockIdx.y, b = blockIdx.z;
    const int cta = bx + TX * (by + TYN * b);
    const int tid = threadIdx.x;

    // ============ Phase 1: transform + bin (first 64 CTAs, 1 pt/thread) ======
    {
        int t = cta * THREADS + tid;
        if (t < BATCH * NP) {
            int pb = t / NP;
            int p  = t - pb * NP;
            float p0 = pts[t * 3 + 0];
            float p1 = pts[t * 3 + 1];
            float p2 = pts[t * 3 + 2];
            const float* Rb = Rm + pb * 9;
            const float* Tb = Tv + pb * 3;

            // row-vector: v[j] = sum_i p[i]*R[i][j] + T[j]
            float xv = p0 * Rb[0] + p1 * Rb[3] + p2 * Rb[6] + Tb[0];
            float yv = p0 * Rb[1] + p1 * Rb[4] + p2 * Rb[7] + Tb[1];
            float zv = p0 * Rb[2] + p1 * Rb[5] + p2 * Rb[8] + Tb[2];

            float f = Fc[pb];
            float x = f * xv / zv;   // IEEE div, matches reference
            float y = f * yv / zv;

            if (zv > 0.0f) {
                float lox = 64.0f * (1.0f - x - RAD) - 0.5f;
                float hix = 64.0f * (1.0f - x + RAD) - 0.5f;
                float loy = 64.0f * (1.0f - y - RAD) - 0.5f;
                float hiy = 64.0f * (1.0f - y + RAD) - 0.5f;
                if (hix >= 0.0f && lox <= (float)(WW - 1) &&
                    hiy >= 0.0f && loy <= (float)(HH - 1)) {
                    int ix0 = max(0, (int)floorf(fmaxf(lox, 0.0f)));
                    int ix1 = min(WW - 1, (int)ceilf(fminf(hix, (float)(WW - 1))));
                    int iy0 = max(0, (int)floorf(fmaxf(loy, 0.0f)));
                    int iy1 = min(HH - 1, (int)ceilf(fminf(hiy, (float)(HH - 1))));
                    if (ix0 <= ix1 && iy0 <= iy1) {
                        int tx0 = ix0 / TILE, tx1 = ix1 / TILE;
                        int ty0 = iy0 / TILE, ty1 = iy1 / TILE;
                        float4 rec = make_float4(x, y, zv, (float)p);
                        for (int ty = ty0; ty <= ty1; ty++)
                            for (int tx = tx0; tx <= tx1; tx++) {
                                int tile = pb * NTILES + ty * TX + tx;
                                int pos = atomicAdd(&g_cnt[tile], 1);
                                g_list[tile * NP + pos] = rec;
                            }
                    }
                }
            }
        }
    }

    // ============ Grid-wide barrier (single co-resident wave guaranteed) =====
    __threadfence();
    __syncthreads();
    if (tid == 0) {
        unsigned e = *(volatile unsigned*)&g_epoch;
        __threadfence();
        unsigned a = atomicAdd(&g_arrive, 1u);
        if (a == NCTA - 1) {
            g_arrive = 0;
            __threadfence();
            atomicAdd(&g_epoch, 1u);
        } else {
            while (*(volatile unsigned*)&g_epoch == e) __nanosleep(64);
        }
        __threadfence();
    }
    __syncthreads();

    // ============ Phase 2: raster (2 lanes per pixel) ========================
    const int tile = b * NTILES + by * TX + bx;
    if (tid == 0) {
        s_n = g_cnt[tile];
        g_cnt[tile] = 0;           // reset for next graph replay (own counter)
    }
    __syncthreads();
    const int n = s_n;
    const float4* __restrict__ list = g_list + tile * NP;

    const int grp = tid >> 1;      // pixel 0..63
    const int sub = tid & 1;       // lane within pixel
    const int lx = grp & (TILE - 1), ly = grp / TILE;
    const int px = bx * TILE + lx;
    const int py = by * TILE + ly;
    const float gx = 1.0f - (px + 0.5f) * (1.0f / 64.0f);
    const float gy = 1.0f - (py + 0.5f) * (1.0f / 64.0f);

    float zb[KK], db[KK], ib[KK];
#pragma unroll
    for (int k = 0; k < KK; k++) { zb[k] = ZINF; db[k] = -1.0f; ib[k] = -1.0f; }

    // ---- Pass 1 (chunked): branch-free FMNMX ladder, lane scans j%2==sub ----
    for (int base = 0; base < n; base += CHUNK) {
        int m = min(CHUNK, n - base);
        __syncthreads();
        for (int i = tid; i < m; i += THREADS) sc[i] = list[base + i];
        __syncthreads();
#pragma unroll 2
        for (int j = sub; j < m; j += 2) {
            float4 c = sc[j];
            float dx = gx - c.x;
            float dy = gy - c.y;
            float d2 = fmaf(dx, dx, dy * dy);
            float key = (d2 < RAD2) ? c.z : ZINF;
#pragma unroll
            for (int k = 0; k < KK; k++) {
                float lo = fminf(zb[k], key);
                key = fmaxf(zb[k], key);
                zb[k] = lo;
            }
        }
    }

    // ---- merge the two sorted 8-lists (branch-free bitonic, shfl partner) ---
    {
        float L[KK];
#pragma unroll
        for (int k = 0; k < KK; k++) {
            float bk = __shfl_xor_sync(0xffffffffu, zb[KK - 1 - k], 1);
            L[k] = fminf(zb[k], bk);          // lower half of bitonic merge
        }
        // sort the bitonic sequence L (3-stage half-cleaner)
#define CE(a, b2) { float lo = fminf(L[a], L[b2]); float hi = fmaxf(L[a], L[b2]); L[a] = lo; L[b2] = hi; }
        CE(0, 4) CE(1, 5) CE(2, 6) CE(3, 7)
        CE(0, 2) CE(1, 3) CE(4, 6) CE(5, 7)
        CE(0, 1) CE(2, 3) CE(4, 5) CE(6, 7)
#undef CE
#pragma unroll
        for (int k = 0; k < KK; k++) zb[k] = L[k];
    }
    const float z7 = zb[KK - 1];

    // ---- Pass 2 (chunked): sparse equality fill of d2/idx (z distinct) ------
    for (int base = 0; base < n; base += CHUNK) {
        int m = min(CHUNK, n - base);
        if (n > CHUNK) {                       // restage only if list didn't fit
            __syncthreads();
            for (int i = tid; i < m; i += THREADS) sc[i] = list[base + i];
            __syncthreads();
        }
#pragma unroll 2
        for (int j = sub; j < m; j += 2) {
            float4 c = sc[j];
            float dx = gx - c.x;
            float dy = gy - c.y;
            float d2 = fmaf(dx, dx, dy * dy);
            if (d2 < RAD2 && c.z <= z7) {
#pragma unroll
                for (int k = 0; k < KK; k++) {
                    if (c.z == zb[k]) { db[k] = d2; ib[k] = c.w; }
                }
            }
        }
    }

    // ---- combine lane fills (unfilled = -1, filled >= 0 => max) -------------
#pragma unroll
    for (int k = 0; k < KK; k++) {
        db[k] = fmaxf(db[k], __shfl_xor_sync(0xffffffffu, db[k], 1));
        ib[k] = fmaxf(ib[k], __shfl_xor_sync(0xffffffffu, ib[k], 1));
    }

    // ---- Output: [idx | zbuf | dists], each [B,H,W,K]; lanes split k --------
    const int N = BATCH * HH * WW * KK;
    const int obase = ((b * HH + py) * WW + px) * KK;
#pragma unroll
    for (int k2 = 0; k2 < KK / 2; k2++) {
        int k = sub * (KK / 2) + k2;
        bool v = zb[k] < ZINF;
        out[obase + k]         = v ? ib[k] : -1.0f;
        out[N + obase + k]     = v ? zb[k] : -1.0f;
        out[2 * N + obase + k] = v ? db[k] : -1.0f;
    }
}

// ---------------------------------------------------------------------------
extern "C" void kernel_launch(void* const* d_in, const int* in_sizes, int n_in,
                              void* d_out, int out_size) {
    const float* pts = (const float*)d_in[0];
    const float* Rm  = (const float*)d_in[1];
    const float* Tv  = (const float*)d_in[2];
    const float* Fc  = (const float*)d_in[3];
    float* out = (float*)d_out;

    raster_fused<<<dim3(TX, TYN, BATCH), THREADS>>>(pts, Rm, Tv, Fc, out);
}

// round 9
// speedup vs baseline: 1.2231x; 1.0654x over previous
#include <cuda_runtime.h>
#include <math.h>

#define BATCH 2
#define NP    4096
#define HH    128
#define WW    128
#define KK    8
#define RAD   0.05f
#define RAD2  (RAD * RAD)
#define TILE  8
#define TX    (WW / TILE)    // 16
#define TYN   (HH / TILE)    // 16
#define NTILES (TX * TYN)    // 256
#define NCTA  (TX * TYN * BATCH)  // 512
#define LPP   4
#define NPIX  (TILE * TILE)  // 64
#define THREADS (NPIX * LPP) // 256
#define PTS_PER_CTA ((BATCH * NP) / NCTA)  // 16
#define CHUNK 512

#define ZINF 3.0e38f

// Global scratch (no cudaMalloc allowed)
__device__ int      g_cnt[BATCH * NTILES];       // zero-init; reset in-kernel
__device__ float4   g_list[BATCH * NTILES * NP];
__device__ unsigned g_arrive = 0;
__device__ unsigned g_epoch  = 0;                // monotonic across replays

__global__ void __launch_bounds__(THREADS) raster_fused(
        const float* __restrict__ pts,
        const float* __restrict__ Rm,
        const float* __restrict__ Tv,
        const float* __restrict__ Fc,
        float* __restrict__ out) {
    __shared__ float4 sc[CHUNK];   // 8 KB
    __shared__ int s_n;

    const int bx = blockIdx.x, by = blockIdx.y, b = blockIdx.z;
    const int cta = bx + TX * (by + TYN * b);
    const int tid = threadIdx.x;

    // ====== Phase 1: transform + bin, spread over ALL CTAs (16 pts each) =====
    if (tid < PTS_PER_CTA) {
        int t = cta * PTS_PER_CTA + tid;
        int pb = t / NP;
        int p  = t - pb * NP;
        float p0 = pts[t * 3 + 0];
        float p1 = pts[t * 3 + 1];
        float p2 = pts[t * 3 + 2];
        const float* Rb = Rm + pb * 9;
        const float* Tb = Tv + pb * 3;

        // row-vector: v[j] = sum_i p[i]*R[i][j] + T[j]
        float xv = p0 * Rb[0] + p1 * Rb[3] + p2 * Rb[6] + Tb[0];
        float yv = p0 * Rb[1] + p1 * Rb[4] + p2 * Rb[7] + Tb[1];
        float zv = p0 * Rb[2] + p1 * Rb[5] + p2 * Rb[8] + Tb[2];

        float f = Fc[pb];
        float x = f * xv / zv;   // IEEE div, matches reference
        float y = f * yv / zv;

        if (zv > 0.0f) {
            float lox = 64.0f * (1.0f - x - RAD) - 0.5f;
            float hix = 64.0f * (1.0f - x + RAD) - 0.5f;
            float loy = 64.0f * (1.0f - y - RAD) - 0.5f;
            float hiy = 64.0f * (1.0f - y + RAD) - 0.5f;
            if (hix >= 0.0f && lox <= (float)(WW - 1) &&
                hiy >= 0.0f && loy <= (float)(HH - 1)) {
                int ix0 = max(0, (int)floorf(fmaxf(lox, 0.0f)));
                int ix1 = min(WW - 1, (int)ceilf(fminf(hix, (float)(WW - 1))));
                int iy0 = max(0, (int)floorf(fmaxf(loy, 0.0f)));
                int iy1 = min(HH - 1, (int)ceilf(fminf(hiy, (float)(HH - 1))));
                if (ix0 <= ix1 && iy0 <= iy1) {
                    int tx0 = ix0 / TILE, tx1 = ix1 / TILE;
                    int ty0 = iy0 / TILE, ty1 = iy1 / TILE;
                    float4 rec = make_float4(x, y, zv, (float)p);
                    for (int ty = ty0; ty <= ty1; ty++)
                        for (int tx = tx0; tx <= tx1; tx++) {
                            int tile = pb * NTILES + ty * TX + tx;
                            int pos = atomicAdd(&g_cnt[tile], 1);
                            g_list[tile * NP + pos] = rec;
                        }
                }
            }
        }
    }

    // ====== Grid-wide barrier (512 CTAs, single co-resident wave) ============
    __threadfence();
    __syncthreads();
    if (tid == 0) {
        unsigned e = *(volatile unsigned*)&g_epoch;
        __threadfence();
        unsigned a = atomicAdd(&g_arrive, 1u);
        if (a == NCTA - 1) {
            g_arrive = 0;
            __threadfence();
            atomicAdd(&g_epoch, 1u);
        } else {
            while (*(volatile unsigned*)&g_epoch == e) __nanosleep(64);
        }
        __threadfence();
    }
    __syncthreads();

    // ====== Phase 2: raster — 4 lanes per pixel ==============================
    const int tile = b * NTILES + by * TX + bx;
    if (tid == 0) {
        s_n = g_cnt[tile];
        g_cnt[tile] = 0;           // reset for next graph replay (own counter)
    }
    __syncthreads();
    const int n = s_n;
    const float4* __restrict__ list = g_list + tile * NP;

    const int grp = tid >> 2;      // pixel 0..63
    const int sub = tid & 3;       // lane within pixel
    const int lx = grp & (TILE - 1), ly = grp / TILE;
    const int px = bx * TILE + lx;
    const int py = by * TILE + ly;
    const float gx = 1.0f - (px + 0.5f) * (1.0f / 64.0f);
    const float gy = 1.0f - (py + 0.5f) * (1.0f / 64.0f);

    float zb[KK];
#pragma unroll
    for (int k = 0; k < KK; k++) zb[k] = ZINF;

    // ---- Pass 1 (chunked): branch-free FMNMX ladder, lane scans j%4==sub ----
    for (int base = 0; base < n; base += CHUNK) {
        int m = min(CHUNK, n - base);
        __syncthreads();
        for (int i = tid; i < m; i += THREADS) sc[i] = list[base + i];
        __syncthreads();
        for (int j = sub; j < m; j += LPP) {
            float4 c = sc[j];
            float dx = gx - c.x;
            float dy = gy - c.y;
            float d2 = fmaf(dx, dx, dy * dy);
            float key = (d2 < RAD2) ? c.z : ZINF;
#pragma unroll
            for (int k = 0; k < KK; k++) {
                float lo = fminf(zb[k], key);
                key = fmaxf(zb[k], key);
                zb[k] = lo;
            }
        }
    }

    // ---- merge 4 sorted lists: two bitonic-merge rounds (xor 1, xor 2) ------
#pragma unroll
    for (int d = 1; d <= 2; d <<= 1) {
        float L[KK];
#pragma unroll
        for (int k = 0; k < KK; k++) {
            float bk = __shfl_xor_sync(0xffffffffu, zb[KK - 1 - k], d);
            L[k] = fminf(zb[k], bk);          // lower half of bitonic merge
        }
#define CE(a, b2) { float lo = fminf(L[a], L[b2]); float hi = fmaxf(L[a], L[b2]); L[a] = lo; L[b2] = hi; }
        CE(0, 4) CE(1, 5) CE(2, 6) CE(3, 7)
        CE(0, 2) CE(1, 3) CE(4, 6) CE(5, 7)
        CE(0, 1) CE(2, 3) CE(4, 5) CE(6, 7)
#undef CE
#pragma unroll
        for (int k = 0; k < KK; k++) zb[k] = L[k];
    }
    const float z7 = zb[KK - 1];

    float db[KK], ib[KK];
#pragma unroll
    for (int k = 0; k < KK; k++) { db[k] = -1.0f; ib[k] = -1.0f; }

    // ---- Pass 2 (chunked): sparse equality fill of d2/idx (z distinct) ------
    for (int base = 0; base < n; base += CHUNK) {
        int m = min(CHUNK, n - base);
        if (n > CHUNK) {                      // restage only if list didn't fit
            __syncthreads();
            for (int i = tid; i < m; i += THREADS) sc[i] = list[base + i];
            __syncthreads();
        }
        for (int j = sub; j < m; j += LPP) {
            float4 c = sc[j];
            float dx = gx - c.x;
            float dy = gy - c.y;
            float d2 = fmaf(dx, dx, dy * dy);
            if (d2 < RAD2 && c.z <= z7) {
#pragma unroll
                for (int k = 0; k < KK; k++) {
                    if (c.z == zb[k]) { db[k] = d2; ib[k] = c.w; }
                }
            }
        }
    }

    // ---- combine lane fills (unfilled = -1, filled >= 0 => max) -------------
#pragma unroll
    for (int d = 1; d <= 2; d <<= 1) {
#pragma unroll
        for (int k = 0; k < KK; k++) {
            db[k] = fmaxf(db[k], __shfl_xor_sync(0xffffffffu, db[k], d));
            ib[k] = fmaxf(ib[k], __shfl_xor_sync(0xffffffffu, ib[k], d));
        }
    }

    // ---- Output: [idx | zbuf | dists], each [B,H,W,K]; lanes split k --------
    const int N = BATCH * HH * WW * KK;
    const int obase = ((b * HH + py) * WW + px) * KK;
#pragma unroll
    for (int k2 = 0; k2 < KK / LPP; k2++) {
        int k = sub * (KK / LPP) + k2;
        bool v = zb[k] < ZINF;
        out[obase + k]         = v ? ib[k] : -1.0f;
        out[N + obase + k]     = v ? zb[k] : -1.0f;
        out[2 * N + obase + k] = v ? db[k] : -1.0f;
    }
}

// ---------------------------------------------------------------------------
extern "C" void kernel_launch(void* const* d_in, const int* in_sizes, int n_in,
                              void* d_out, int out_size) {
    const float* pts = (const float*)d_in[0];
    const float* Rm  = (const float*)d_in[1];
    const float* Tv  = (const float*)d_in[2];
    const float* Fc  = (const float*)d_in[3];
    float* out = (float*)d_out;

    raster_fused<<<dim3(TX, TYN, BATCH), THREADS>>>(pts, Rm, Tv, Fc, out);
}